// round 17
// baseline (speedup 1.0000x reference)
#include <cuda_runtime.h>

#define BB 256
#define TT 64
#define NN 128
#define HH 512
#define G4 2048
#define KK 640          // N + H
#define NCTA 128
#define GRP 32          // CTAs per independent group

// ---------------- device scratch (static, allocation-free) ----------------
__device__ __align__(16) float g_z2[BB * NN * TT];   // (b,n,s) s-contiguous, 8 MB
__device__ __align__(16) float g_A[2][BB * KK];      // double-buffered: [wx(128) | h(512)] per b
__device__ __align__(16) float g_c[BB * HH];         // cell state
__device__ __align__(16) float g_Wc[KK * G4];        // combined weights, (k, jp) jp-fastest
__device__ __align__(16) float g_bias[G4];           // permuted b_ih + b_hh
__device__ unsigned g_bars[128];                     // 4 counters, 128B apart

// ---------------- math helpers ----------------
__device__ __forceinline__ float sigm(float x) {
    return 1.0f / (1.0f + __expf(-x));
}
__device__ __forceinline__ float tanh_acc(float x) {
    return 2.0f / (1.0f + __expf(-2.0f * x)) - 1.0f;
}
__device__ __forceinline__ float tanh_fast(float x) {
    float y;
    asm("tanh.approx.f32 %0, %1;" : "=f"(y) : "f"(x));
    return y;
}
__device__ __forceinline__ void fma2(unsigned long long& acc,
                                     unsigned long long a, unsigned long long b) {
    asm("fma.rn.f32x2 %0, %1, %2, %0;" : "+l"(acc) : "l"(a), "l"(b));
}
__device__ __forceinline__ unsigned long long dup2(float v) {
    unsigned long long r;
    asm("mov.b64 %0, {%1, %1};" : "=l"(r) : "f"(v));
    return r;
}
__device__ __forceinline__ unsigned long long pack2(float lo, float hi) {
    unsigned long long r;
    asm("mov.b64 %0, {%1, %2};" : "=l"(r) : "f"(lo), "f"(hi));
    return r;
}
__device__ __forceinline__ void unpack2(float& lo, float& hi, unsigned long long v) {
    asm("mov.b64 {%0, %1}, %2;" : "=f"(lo), "=f"(hi) : "l"(v));
}

// ---------------- per-group barrier (32 CTAs) ------------------------------
__device__ __forceinline__ void group_sync(unsigned& epoch, unsigned* ctr) {
    __syncthreads();
    if (threadIdx.x == 0) {
        ++epoch;
        __threadfence();                       // release prior global writes
        atomicAdd(ctr, 1u);                    // returnless -> RED
        unsigned need = epoch * GRP;
        unsigned cur;
        do {
            asm volatile("ld.acquire.gpu.u32 %0, [%1];" : "=r"(cur) : "l"(ctr));
        } while (cur < need);
    }
    __syncthreads();
}

// ---------------- fused prep + z2 precompute -------------------------------
__global__ void setup_kernel(const float* __restrict__ dx,
                             const float* __restrict__ W_a2,
                             const float* __restrict__ b_a2,
                             const float* __restrict__ W_ih,
                             const float* __restrict__ W_hh,
                             const float* __restrict__ b_ih,
                             const float* __restrict__ b_hh)
{
    if (blockIdx.x < 1024) {
        __shared__ float xs[TT][32];
        __shared__ float wa2[TT][65];
        int b  = blockIdx.x >> 2;
        int n0 = (blockIdx.x & 3) << 5;
        int tid = threadIdx.x;
        for (int i = tid; i < TT * 32; i += 256) {
            int t = i >> 5, j = i & 31;
            xs[t][j] = dx[(b * TT + t) * NN + n0 + j];
        }
        for (int i = tid; i < TT * TT; i += 256)
            wa2[i >> 6][i & 63] = W_a2[i];
        __syncthreads();
        #pragma unroll
        for (int p = 0; p < 8; ++p) {
            int id = p * 256 + tid;
            int s = id & 63, nj = id >> 6;
            float acc = b_a2[s];
            #pragma unroll 8
            for (int t = 0; t < TT; ++t)
                acc += xs[t][nj] * wa2[s][t];
            g_z2[(((b << 7) + n0 + nj) << 6) + s] = acc;
        }
    } else {
        int idx = (blockIdx.x - 1024) * blockDim.x + threadIdx.x;
        const int stride = 1024 * 256;
        for (int i = idx; i < KK * G4; i += stride) {
            int k  = i >> 11;
            int jp = i & 2047;
            int j  = (jp & 3) * HH + (jp >> 2);
            g_Wc[i] = (k < NN) ? W_ih[j * NN + k] : W_hh[j * HH + (k - NN)];
        }
        for (int i = idx; i < G4; i += stride) {
            int j = (i & 3) * HH + (i >> 2);
            g_bias[i] = b_ih[j] + b_hh[j];
        }
        for (int i = idx; i < BB * HH; i += stride) {
            int b = i >> 9, j = i & 511;
            g_c[i] = 0.0f;
            g_A[0][b * KK + NN + j] = 0.0f;
            g_A[1][b * KK + NN + j] = 0.0f;
        }
        if (idx < 128) g_bars[idx] = 0u;
    }
}

// ---------------- persistent recurrent kernel ------------------------------
// dynamic smem: this CTA's full W slice, [640][64] floats = 160 KB
extern __shared__ float Wsm[];

__global__ void __launch_bounds__(512, 1) lstm_kernel(
    const float* __restrict__ dx,
    const float* __restrict__ W_a1,
    const float* __restrict__ b_a1,
    const float* __restrict__ W_a3,
    const float* __restrict__ b_a3,
    float* __restrict__ out)
{
    __shared__ __align__(16) float z1s[2][64];
    __shared__ __align__(16) float es[2][128];
    __shared__ __align__(16) float wa3s[64];
    __shared__ __align__(16) float ba1s[64];
    __shared__ __align__(16) float As[2][64][68];        // double-buffered 64-k A tile [k][b]
    __shared__ __align__(16) unsigned long long red[256][8];  // k-half reduction buffer

    const int tid  = threadIdx.x;
    const int cta  = blockIdx.x;
    const int lane = tid & 31;
    const int warp = tid >> 5;                // 0..15

    if (tid < 64) { wa3s[tid] = W_a3[tid]; ba1s[tid] = b_a1[tid]; }
    const float ba3 = b_a3[0];
    unsigned epoch = 0u;
    unsigned* ctr = &g_bars[(cta >> 5) << 5];   // this group's counter (128B apart)

    // tile assignment: 4 b-groups x 32 gate-slices
    const int bg  = cta >> 5;
    const int jg  = cta & 31;
    const int b0  = bg << 6;
    const int jp0 = jg << 6;

    // GEMM compute indices (ALL 16 warps; 4b x 4j per thread; k-half by warp)
    const int tx  = tid & 15;
    const int ty  = (tid >> 4) & 15;          // 0..15 for both thread-halves
    const int kb  = (warp < 8) ? 0 : 32;      // k-half base within 64-k tile
    const int hj  = (jg << 4) + tx;
    const float bs0 = g_bias[jp0 + (tx << 2) + 0];
    const float bs1 = g_bias[jp0 + (tx << 2) + 1];
    const float bs2 = g_bias[jp0 + (tx << 2) + 2];
    const float bs3 = g_bias[jp0 + (tx << 2) + 3];

    // staging indices (all 16 warps): 8 cols per thread, 64-k tile
    const int kl = tid & 63;                  // k within tile
    const int cb = (tid >> 6) << 3;           // col base 0..56

    // attention batch assignment: 2 b per CTA
    const int ba = cta << 1;

    // load this CTA's W slice into shared, once
    {
        const int nf4 = KK * 64 / 4;
        float4* dst = (float4*)Wsm;
        for (int i = tid; i < nf4; i += 512) {
            int k = i >> 4, c4 = i & 15;
            dst[i] = *(const float4*)&g_Wc[k * G4 + jp0 + (c4 << 2)];
        }
    }
    __syncthreads();

    for (int t = 0; t < TT; ++t) {
        const float* Acur = g_A[t & 1];
        float*       Anxt = g_A[(t & 1) ^ 1];

        // ===== Phase A1 (16 warps): z1[b,s] = [h|c].W_a1[s] + b_a1[s] =====
        // warp w: b-half bl = w>>3, s in [8*(w&7), 8*(w&7)+8)
        {
            const int bl = warp >> 3;
            const int sb = (warp & 7) << 3;
            const int b = ba + bl;
            const float4* hp = (const float4*)(Acur + (size_t)b * KK + NN) + lane;
            const float4* cp = (const float4*)(g_c + (b << 9)) + lane;
            float4 xh[4], xc[4];
            #pragma unroll
            for (int k = 0; k < 4; ++k) {
                xh[k] = __ldcg(hp + k * 32);
                xc[k] = __ldcg(cp + k * 32);
            }
            #pragma unroll 2
            for (int i = 0; i < 8; ++i) {
                int s = sb + i;
                const float4* wrow = (const float4*)(W_a1 + (s << 10)) + lane;
                float a = 0.f;
                #pragma unroll
                for (int k = 0; k < 4; ++k) {
                    float4 w = __ldcs(wrow + k * 32);
                    a += w.x * xh[k].x + w.y * xh[k].y + w.z * xh[k].z + w.w * xh[k].w;
                }
                #pragma unroll
                for (int k = 0; k < 4; ++k) {
                    float4 w = __ldcs(wrow + 128 + k * 32);
                    a += w.x * xc[k].x + w.y * xc[k].y + w.z * xc[k].z + w.w * xc[k].w;
                }
                #pragma unroll
                for (int d = 16; d > 0; d >>= 1)
                    a += __shfl_xor_sync(0xffffffffu, a, d);
                if (lane == 0)
                    z1s[bl][s] = a + ba1s[s];
            }
        }
        __syncthreads();

        // ===== Phase A2 (16 warps): e[b,n] = sum_s tanh(z1+z2)*W_a3[s]+b_a3
        {
            const int bl   = warp & 1;
            const int nh   = warp >> 1;
            const int nsub = lane >> 3;
            const int sidx = (lane & 7) << 3;
            const int b = ba + bl;
            float4 z1a0 = *(const float4*)&z1s[bl][sidx];
            float4 z1a1 = *(const float4*)&z1s[bl][sidx + 4];
            float4 wa0  = *(const float4*)&wa3s[sidx];
            float4 wa1  = *(const float4*)&wa3s[sidx + 4];
            #pragma unroll
            for (int pass = 0; pass < 4; ++pass) {
                int n = (nh << 4) + (pass << 2) + nsub;
                const float4* z2p = (const float4*)(g_z2 + (((b << 7) + n) << 6) + sidx);
                float4 q0 = __ldg(z2p);
                float4 q1 = __ldg(z2p + 1);
                float v = tanh_fast(z1a0.x + q0.x) * wa0.x
                        + tanh_fast(z1a0.y + q0.y) * wa0.y
                        + tanh_fast(z1a0.z + q0.z) * wa0.z
                        + tanh_fast(z1a0.w + q0.w) * wa0.w
                        + tanh_fast(z1a1.x + q1.x) * wa1.x
                        + tanh_fast(z1a1.y + q1.y) * wa1.y
                        + tanh_fast(z1a1.z + q1.z) * wa1.z
                        + tanh_fast(z1a1.w + q1.w) * wa1.w;
                #pragma unroll
                for (int d = 4; d > 0; d >>= 1)
                    v += __shfl_xor_sync(0xffffffffu, v, d);
                if ((lane & 7) == 0) es[bl][n] = v + ba3;
            }
        }
        __syncthreads();

        // ===== softmax over n + wx = w * x_t (warps 0,1) =====
        if (warp < 2) {
            int b = ba + warp;
            float v0 = es[warp][lane],      v1 = es[warp][lane + 32];
            float v2 = es[warp][lane + 64], v3 = es[warp][lane + 96];
            float m = fmaxf(fmaxf(v0, v1), fmaxf(v2, v3));
            #pragma unroll
            for (int d = 16; d > 0; d >>= 1)
                m = fmaxf(m, __shfl_xor_sync(0xffffffffu, m, d));
            float e0 = __expf(v0 - m), e1 = __expf(v1 - m);
            float e2 = __expf(v2 - m), e3 = __expf(v3 - m);
            float s = e0 + e1 + e2 + e3;
            #pragma unroll
            for (int d = 16; d > 0; d >>= 1)
                s += __shfl_xor_sync(0xffffffffu, s, d);
            float inv = 1.0f / s;
            const float* xr = dx + (((b << 6) + t) << 7);
            float* wxr = (float*)Acur + (size_t)b * KK;
            __stcg(&wxr[lane],      e0 * inv * xr[lane]);
            __stcg(&wxr[lane + 32], e1 * inv * xr[lane + 32]);
            __stcg(&wxr[lane + 64], e2 * inv * xr[lane + 64]);
            __stcg(&wxr[lane + 96], e3 * inv * xr[lane + 96]);
        }
        group_sync(epoch, ctr);   // group's wx(t) + h,c(t-1) globally visible

        // ===== GEMM: gates [64b x 64j] = A[64x640] @ Wc[640x64] =============
        // 10 iterations of 64-k tiles. All 16 warps stage AND compute:
        // warps 0-7 take k-local [0,32), warps 8-15 take [32,64) (k-split),
        // partial sums merged once per step through smem.
        unsigned long long acc2[2][4];
        #pragma unroll
        for (int i = 0; i < 2; ++i)
            #pragma unroll
            for (int j = 0; j < 4; ++j) acc2[i][j] = 0ull;

        float r[8];
        #pragma unroll
        for (int q = 0; q < 8; ++q)    // prefetch tile 0
            r[q] = __ldcg(&Acur[(size_t)(b0 + cb + q) * KK + kl]);

        for (int it = 0; it < 10; ++it) {
            const int cur = it & 1;
            #pragma unroll
            for (int q = 0; q < 8; ++q)
                As[cur][kl][cb + q] = r[q];
            if (it < 9) {                          // prefetch overlaps the barrier
                int k0n = (it + 1) << 6;
                #pragma unroll
                for (int q = 0; q < 8; ++q)
                    r[q] = __ldcg(&Acur[(size_t)(b0 + cb + q) * KK + k0n + kl]);
            }
            __syncthreads();
            const int k0 = (it << 6) + kb;
            #pragma unroll
            for (int k = 0; k < 32; ++k) {
                float4 av = *(const float4*)&As[cur][kb + k][ty << 2];   // 2 b-pairs
                float4 wv = *(const float4*)&Wsm[(k0 + k) * 64 + (tx << 2)];
                unsigned long long ap0 = ((const unsigned long long*)&av)[0];
                unsigned long long ap1 = ((const unsigned long long*)&av)[1];
                unsigned long long w0 = dup2(wv.x), w1 = dup2(wv.y);
                unsigned long long w2 = dup2(wv.z), w3 = dup2(wv.w);
                fma2(acc2[0][0], ap0, w0); fma2(acc2[0][1], ap0, w1);
                fma2(acc2[0][2], ap0, w2); fma2(acc2[0][3], ap0, w3);
                fma2(acc2[1][0], ap1, w0); fma2(acc2[1][1], ap1, w1);
                fma2(acc2[1][2], ap1, w2); fma2(acc2[1][3], ap1, w3);
            }
            // single sync per iteration: store(it+1) targets the other buffer
            // whose last readers (compute it-1) are ordered before sync(it)
        }

        // ===== merge k-halves: upper warps deposit partials, lower add ======
        if (tid >= 256) {
            #pragma unroll
            for (int i = 0; i < 2; ++i)
                #pragma unroll
                for (int j = 0; j < 4; ++j)
                    red[tid - 256][(i << 2) + j] = acc2[i][j];
        }
        __syncthreads();

        // ===== LSTM pointwise (warps 0-7) ===================================
        if (tid < 256) {
            #pragma unroll
            for (int i = 0; i < 2; ++i)
                #pragma unroll
                for (int j = 0; j < 4; ++j) {
                    float al, ah, bl2, bh2;
                    unpack2(al, ah, acc2[i][j]);
                    unpack2(bl2, bh2, red[tid][(i << 2) + j]);
                    acc2[i][j] = pack2(al + bl2, ah + bh2);
                }
            #pragma unroll
            for (int pr = 0; pr < 2; ++pr) {
                float gi_l, gi_h, gf_l, gf_h, gg_l, gg_h, go_l, go_h;
                unpack2(gi_l, gi_h, acc2[pr][0]);
                unpack2(gf_l, gf_h, acc2[pr][1]);
                unpack2(gg_l, gg_h, acc2[pr][2]);
                unpack2(go_l, go_h, acc2[pr][3]);
                #pragma unroll
                for (int lh = 0; lh < 2; ++lh) {
                    int b = b0 + (ty << 2) + (pr << 1) + lh;
                    float gi = (lh ? gi_h : gi_l) + bs0;
                    float gf = (lh ? gf_h : gf_l) + bs1;
                    float gg = (lh ? gg_h : gg_l) + bs2;
                    float go = (lh ? go_h : go_l) + bs3;
                    float c_old = __ldcg(&g_c[(b << 9) + hj]);
                    float cn = sigm(gf) * c_old + sigm(gi) * tanh_acc(gg);
                    float hn = sigm(go) * tanh_acc(cn);
                    __stcg(&g_c[(b << 9) + hj], cn);
                    __stcg(&Anxt[(size_t)b * KK + NN + hj], hn);
                    __stcs(&out[(((b << 6) + t) << 9) + hj], hn);
                }
            }
        }
        group_sync(epoch, ctr);   // group's h(t), c(t) visible for next step
    }
}

// ---------------- launch ----------------
extern "C" void kernel_launch(void* const* d_in, const int* in_sizes, int n_in,
                              void* d_out, int out_size)
{
    const float* dx   = (const float*)d_in[0];
    const float* W_a1 = (const float*)d_in[1];
    const float* b_a1 = (const float*)d_in[2];
    const float* W_a2 = (const float*)d_in[3];
    const float* b_a2 = (const float*)d_in[4];
    const float* W_a3 = (const float*)d_in[5];
    const float* b_a3 = (const float*)d_in[6];
    const float* W_ih = (const float*)d_in[7];
    const float* W_hh = (const float*)d_in[8];
    const float* b_ih = (const float*)d_in[9];
    const float* b_hh = (const float*)d_in[10];
    float* out = (float*)d_out;

    const int wsm_bytes = KK * 64 * sizeof(float);   // 160 KB dynamic smem
    cudaFuncSetAttribute(lstm_kernel, cudaFuncAttributeMaxDynamicSharedMemorySize, wsm_bytes);

    setup_kernel<<<2048, 256>>>(dx, W_a2, b_a2, W_ih, W_hh, b_ih, b_hh);
    lstm_kernel<<<NCTA, 512, wsm_bytes>>>(dx, W_a1, b_a1, W_a3, b_a3, out);
}